// round 17
// baseline (speedup 1.0000x reference)
#include <cuda_runtime.h>
#include <cstdint>

#define B_DIM 4096
#define K_DIM 64
#define D_DIM 512
#define POOL_N 1000000
#define THREADS 1024
#define NWARP (THREADS / 32)           // 32 warps
#define ROWS_PER_WARP (K_DIM / NWARP)  // 2 rows per warp

// smem: partials[NWARP][D] | x[D]  = 64KB + 2KB
#define SMEM_FLOATS (NWARP * D_DIM + D_DIM)
#define SMEM_BYTES (SMEM_FLOATS * sizeof(float))

__global__ void __launch_bounds__(THREADS, 1)
sparse_exec_kernel(const float* __restrict__ x,
                   const int* __restrict__ indices,
                   const float* __restrict__ weights,
                   const float* __restrict__ pool,
                   float* __restrict__ out) {
    extern __shared__ float smem[];
    float* s_part = smem;                      // NWARP * D
    float* s_x    = smem + NWARP * D_DIM;      // D

    const int b    = blockIdx.x;
    const int tid  = threadIdx.x;
    const int warp = tid >> 5;
    const int lane = tid & 31;

    // ---- 1. indices + weights first (critical chain: idx -> pool) ----
    int idxs[ROWS_PER_WARP];
    float w[ROWS_PER_WARP];
#pragma unroll
    for (int r = 0; r < ROWS_PER_WARP; r++) {
        int k = warp * ROWS_PER_WARP + r;
        idxs[r] = indices[(size_t)b * K_DIM + k];
        w[r]    = __ldg(&weights[(size_t)b * K_DIM + k]);
    }

    // ---- 2. x load (threads 0..511), overlaps index latency ----
    float xv = 0.0f;
    if (tid < D_DIM) xv = x[(size_t)b * D_DIM + tid];

    // ---- 3. clamp + fire all 8 pool LDG.128 (MLP=8/thread) ----
#pragma unroll
    for (int r = 0; r < ROWS_PER_WARP; r++) {
        int t = idxs[r];
        idxs[r] = t < 0 ? 0 : (t >= POOL_N ? POOL_N - 1 : t);
    }
    float4 v[ROWS_PER_WARP][4];
#pragma unroll
    for (int r = 0; r < ROWS_PER_WARP; r++) {
        const float4* prow = (const float4*)(pool + (size_t)idxs[r] * D_DIM);
#pragma unroll
        for (int i = 0; i < 4; i++)
            v[r][i] = __ldg(&prow[i * 32 + lane]);
    }

    // ---- 4. x -> smem + barrier (hidden behind pool-load latency) ----
    if (tid < D_DIM) s_x[tid] = xv;
    __syncthreads();

    const float4* sx4 = (const float4*)s_x;
    float4 xr[4];
#pragma unroll
    for (int i = 0; i < 4; i++)
        xr[i] = sx4[i * 32 + lane];

    // ---- 5. dots + warp reduce ----
    float dot[ROWS_PER_WARP];
#pragma unroll
    for (int r = 0; r < ROWS_PER_WARP; r++) {
        float d = 0.0f;
#pragma unroll
        for (int i = 0; i < 4; i++)
            d += v[r][i].x * xr[i].x + v[r][i].y * xr[i].y
               + v[r][i].z * xr[i].z + v[r][i].w * xr[i].w;
#pragma unroll
        for (int off = 16; off; off >>= 1)
            d += __shfl_xor_sync(0xffffffffu, d, off);
        dot[r] = d;
    }

    float wa[ROWS_PER_WARP];
#pragma unroll
    for (int r = 0; r < ROWS_PER_WARP; r++)
        wa[r] = tanhf(dot[r]) * w[r];

    // ---- 6. per-warp weighted partial from registers ----
    float4* pw = (float4*)(s_part + warp * D_DIM);
#pragma unroll
    for (int i = 0; i < 4; i++) {
        float4 p;
        p.x = wa[0] * v[0][i].x + wa[1] * v[1][i].x;
        p.y = wa[0] * v[0][i].y + wa[1] * v[1][i].y;
        p.z = wa[0] * v[0][i].z + wa[1] * v[1][i].z;
        p.w = wa[0] * v[0][i].w + wa[1] * v[1][i].w;
        pw[i * 32 + lane] = p;
    }
    __syncthreads();

    // ---- 7. split 32-way reduction across thread halves ----
    // half 0 (tid 0..511):   sums partials 0..15 of element d
    // half 1 (tid 512..1023): sums partials 16..31 of element d,
    //                         stashes result into s_part[16*D + d]
    //                         (a slot only half-1 reads, already consumed).
    {
        const int d    = tid & (D_DIM - 1);
        const int half = tid >> 9;
        const int base = half * (NWARP / 2);
        float acc = 0.0f;
#pragma unroll
        for (int wq = 0; wq < NWARP / 2; wq++)
            acc += s_part[(base + wq) * D_DIM + d];

        if (half == 1)
            s_part[(NWARP / 2) * D_DIM + d] = acc;   // safe: only half-1 ever read these slots
        __syncthreads();
        if (half == 0)
            out[(size_t)b * D_DIM + d] = s_x[d] + acc + s_part[(NWARP / 2) * D_DIM + d];
    }
}

extern "C" void kernel_launch(void* const* d_in, const int* in_sizes, int n_in,
                              void* d_out, int out_size) {
    const float* x       = (const float*)d_in[0];
    const int*   indices = (const int*)d_in[1];
    const float* weights = (const float*)d_in[2];
    const float* pool    = (const float*)d_in[3];
    float*       out     = (float*)d_out;

    cudaFuncSetAttribute(sparse_exec_kernel,
                         cudaFuncAttributeMaxDynamicSharedMemorySize, SMEM_BYTES);

    sparse_exec_kernel<<<B_DIM, THREADS, SMEM_BYTES>>>(x, indices, weights, pool, out);
}